// round 1
// baseline (speedup 1.0000x reference)
#include <cuda_runtime.h>

#define N_NODES_MAX 50000
#define C_IN   64
#define C_OUT  64
#define KPRE   67    // feat(64) + src pos(3) -> precomputable part of C_MSG
#define C_MSG  71
#define NUM_TYPES 2

// Scratch for precomputed per-node, per-type transformed features (+bias folded in).
__device__ float g_z[(size_t)N_NODES_MAX * NUM_TYPES * C_OUT];

// ---------- float <-> orderable-uint encoding for atomicMax on fp32 ----------
__device__ __forceinline__ unsigned enc_f32(float f) {
    unsigned u = __float_as_uint(f);
    return (u & 0x80000000u) ? ~u : (u | 0x80000000u);
}
// enc(-inf) == 0x007FFFFF
#define ENC_NEG_INF 0x007FFFFFu

__global__ void init_kernel(unsigned* __restrict__ out, int n) {
    int i = blockIdx.x * blockDim.x + threadIdx.x;
    if (i < n) out[i] = ENC_NEG_INF;
}

// ---------- Phase A: z[n,t,c] = sum_{k<67} x[n,k] * W[t,k,c] + b[t,c] ----------
// x[n,k] = feat[n,k] for k<64, pos[n,k-64] for k in 64..66.
// Block: 256 threads = 2 (types) x 64 (channels) x 2 (node slots); each thread
// register-blocks 2 nodes -> 4 nodes per block iteration.
__global__ void precompute_kernel(const float* __restrict__ feat,
                                  const float* __restrict__ pos,
                                  const float* __restrict__ W,
                                  const float* __restrict__ b,
                                  int n_nodes) {
    __shared__ float W_sh[NUM_TYPES][KPRE][C_OUT];   // 34.3 KB
    __shared__ float b_sh[NUM_TYPES][C_OUT];
    __shared__ float x_sh[4][KPRE];

    for (int i = threadIdx.x; i < NUM_TYPES * KPRE * C_OUT; i += blockDim.x) {
        int t = i / (KPRE * C_OUT);
        int r = i % (KPRE * C_OUT);
        int k = r / C_OUT, c = r % C_OUT;
        W_sh[t][k][c] = W[(t * C_MSG + k) * C_OUT + c];
    }
    for (int i = threadIdx.x; i < NUM_TYPES * C_OUT; i += blockDim.x)
        b_sh[i / C_OUT][i % C_OUT] = b[i];
    __syncthreads();

    const int tid = threadIdx.x;
    const int t = (tid >> 6) & 1;
    const int c = tid & 63;
    const int l = tid >> 7;   // 0 or 1

    const int ngroups = (n_nodes + 3) >> 2;
    for (int g = blockIdx.x; g < ngroups; g += gridDim.x) {
        const int base = g * 4;
        __syncthreads();   // previous iteration's x_sh reads complete
        for (int i = tid; i < 4 * KPRE; i += blockDim.x) {
            int nl = i / KPRE, k = i % KPRE;
            int n = base + nl;
            float v = 0.f;
            if (n < n_nodes)
                v = (k < C_IN) ? feat[(size_t)n * C_IN + k]
                               : pos[(size_t)n * 3 + (k - C_IN)];
            x_sh[nl][k] = v;
        }
        __syncthreads();

        float acc0 = b_sh[t][c];
        float acc1 = acc0;
        #pragma unroll
        for (int k = 0; k < KPRE; k++) {
            float w = W_sh[t][k][c];
            acc0 = fmaf(x_sh[l][k],     w, acc0);
            acc1 = fmaf(x_sh[l + 2][k], w, acc1);
        }
        int n0 = base + l, n1 = base + l + 2;
        if (n0 < n_nodes) g_z[((size_t)n0 * NUM_TYPES + t) * C_OUT + c] = acc0;
        if (n1 < n_nodes) g_z[((size_t)n1 * NUM_TYPES + t) * C_OUT + c] = acc1;
    }
}

// ---------- Phase B: per-edge finish + scatter-max ----------
// Warp processes 32 edges per round: coalesced metadata loads, then per-edge
// broadcast via shfl. Each lane handles channels (lane, lane+32).
__global__ void edge_kernel(const float* __restrict__ pos,
                            const float* __restrict__ W,
                            const int* __restrict__ src,
                            const int* __restrict__ dst,
                            const int* __restrict__ attr,
                            unsigned* __restrict__ out,
                            int n_edges) {
    __shared__ float wp[NUM_TYPES * 4 * C_OUT];   // W rows 67..70 per type (2 KB)
    for (int i = threadIdx.x; i < NUM_TYPES * 4 * C_OUT; i += blockDim.x) {
        int t = i / (4 * C_OUT);
        int r = i % (4 * C_OUT);
        int k = KPRE + r / C_OUT, c = r % C_OUT;
        wp[i] = W[(t * C_MSG + k) * C_OUT + c];
    }
    __syncthreads();

    const int lane = threadIdx.x & 31;
    const int gw = (blockIdx.x * blockDim.x + threadIdx.x) >> 5;
    const int nw = (gridDim.x * blockDim.x) >> 5;

    for (int base = gw * 32; base < n_edges; base += nw * 32) {
        int e = base + lane;
        int s = 0, d = 0, t = 0;
        float dx = 0.f, dy = 0.f, dz = 0.f;
        if (e < n_edges) {
            s = src[e]; d = dst[e]; t = attr[e];
            float ax = pos[3 * s], ay = pos[3 * s + 1], az = pos[3 * s + 2];
            dx = pos[3 * d]     - ax;
            dy = pos[3 * d + 1] - ay;
            dz = pos[3 * d + 2] - az;
        }
        int cnt = n_edges - base;
        if (cnt > 32) cnt = 32;
        for (int i = 0; i < cnt; i++) {
            int si = __shfl_sync(0xffffffffu, s, i);
            int di = __shfl_sync(0xffffffffu, d, i);
            int ti = __shfl_sync(0xffffffffu, t, i);
            float dxi = __shfl_sync(0xffffffffu, dx, i);
            float dyi = __shfl_sync(0xffffffffu, dy, i);
            float dzi = __shfl_sync(0xffffffffu, dz, i);
            float dist = sqrtf(fmaf(dxi, dxi, fmaf(dyi, dyi, dzi * dzi)));

            const float* zr = g_z + ((size_t)si * NUM_TYPES + ti) * C_OUT;
            const float* w0 = wp + ti * 4 * C_OUT;

            float y0 = zr[lane];
            y0 = fmaf(dxi,  w0[lane],             y0);
            y0 = fmaf(dyi,  w0[C_OUT + lane],     y0);
            y0 = fmaf(dzi,  w0[2 * C_OUT + lane], y0);
            y0 = fmaf(dist, w0[3 * C_OUT + lane], y0);

            float y1 = zr[lane + 32];
            y1 = fmaf(dxi,  w0[lane + 32],             y1);
            y1 = fmaf(dyi,  w0[C_OUT + lane + 32],     y1);
            y1 = fmaf(dzi,  w0[2 * C_OUT + lane + 32], y1);
            y1 = fmaf(dist, w0[3 * C_OUT + lane + 32], y1);

            unsigned u0 = enc_f32(y0);
            unsigned u1 = enc_f32(y1);
            unsigned* o = out + (size_t)di * C_OUT;
            // test-before-atomic: stored value only grows, so a stale read can
            // only cause an extra atomic, never an incorrect skip.
            if (o[lane] < u0)      atomicMax(o + lane, u0);
            if (o[lane + 32] < u1) atomicMax(o + lane + 32, u1);
        }
    }
}

// ---------- decode orderable-uint back to float; empty(-inf) -> 0 ----------
__global__ void decode_kernel(unsigned* __restrict__ out, int n) {
    int i = blockIdx.x * blockDim.x + threadIdx.x;
    if (i < n) {
        unsigned u = out[i];
        unsigned bits = (u & 0x80000000u) ? (u & 0x7FFFFFFFu) : ~u;
        float f = __uint_as_float(bits);
        if (!isfinite(f)) f = 0.f;
        reinterpret_cast<float*>(out)[i] = f;
    }
}

extern "C" void kernel_launch(void* const* d_in, const int* in_sizes, int n_in,
                              void* d_out, int out_size) {
    const float* feat = (const float*)d_in[0];
    const float* pos  = (const float*)d_in[1];
    const float* W    = (const float*)d_in[2];
    const float* b    = (const float*)d_in[3];
    const int* ei     = (const int*)d_in[4];
    const int* attr   = (const int*)d_in[5];

    int n_nodes = in_sizes[0] / C_IN;
    int n_edges = in_sizes[5];
    unsigned* out = (unsigned*)d_out;

    init_kernel<<<(out_size + 255) / 256, 256>>>(out, out_size);
    precompute_kernel<<<1184, 256>>>(feat, pos, W, b, n_nodes);
    edge_kernel<<<2048, 256>>>(pos, W, ei, ei + n_edges, attr, out, n_edges);
    decode_kernel<<<(out_size + 255) / 256, 256>>>(out, out_size);
}